// round 15
// baseline (speedup 1.0000x reference)
#include <cuda_runtime.h>
#include <cuda_fp16.h>
#include <math.h>
#include <stdint.h>

// ---------------- problem constants ----------------
constexpr int E    = 8;
constexpr int D    = 512;
constexpr int HH   = 1024;
constexpr int NTOK = 8192;
constexpr int AMAX = NTOK * 2;     // exactly 2 assignments per token
constexpr int NTILE = 64;          // routing tiles of 128 tokens
constexpr int MAXT  = 136;         // max total m-tiles: 128 + E
constexpr int GRID  = 304;         // persistent CTAs (2/SM on 152 SMs)

// static aux job layout: [0,512) router, [512,768) conv1, [768,1024) conv2
constexpr int JR   = 512;
constexpr int NC1  = 256;
constexpr int NC2  = 256;
constexpr int NAUX = JR + NC1 + NC2;   // 1024
constexpr int NS   = 64;               // scatter jobs (CTAs 1..64)
// dynamic GEMM jobs
constexpr int NJ1  = MAXT * 8;
constexpr int NJOBS = MAXT * 12;

// ---------------- device scratch (static; no allocation) ----------------
__device__ __half g_xh[(size_t)NTOK * D];      // x in fp16
__device__ __half g_w1h[(size_t)E * HH * D];   // [E][H][D]  (w1 transposed, fp16)
__device__ __half g_w2h[(size_t)E * D * HH];   // [E][D][H]  (w2 transposed, fp16)
__device__ __half g_hh[(size_t)AMAX * HH];     // gelu(h) fp16

__device__ int   g_tok[AMAX];
__device__ float g_wt[AMAX];
__device__ int   g_topi[NTOK * 2];
__device__ float g_topw[NTOK * 2];
__device__ int   g_count[E];
__device__ int   g_offs[E + 1];
__device__ int   g_tilecnt[NTILE][E];
__device__ int   g_tileoff[NTILE][E];
__device__ int   g_tlist[MAXT];
__device__ int   g_ntile;
__device__ int   g_done[MAXT];     // per-m-tile GEMM1 completion count
__device__ int   g_job;            // dynamic GEMM job counter
__device__ int   g_c1done, g_c2done, g_scatdone, g_routdone, g_offsdone;

// ---------------- PTX helpers (baseline sm_80/90; no arch-'a' features) ----
__device__ __forceinline__ uint32_t smem_u32(const void* p) {
    uint32_t a;
    asm("{ .reg .u64 t; cvta.to.shared.u64 t, %1; cvt.u32.u64 %0, t; }" : "=r"(a) : "l"(p));
    return a;
}
__device__ __forceinline__ void cp_async16(uint32_t dst, const void* src) {
    asm volatile("cp.async.cg.shared.global [%0], [%1], 16;" :: "r"(dst), "l"(src));
}
#define CP_COMMIT() asm volatile("cp.async.commit_group;" ::: "memory")
#define CP_WAIT(n)  asm volatile("cp.async.wait_group %0;" :: "n"(n) : "memory")

__device__ __forceinline__ void ldmatrix_x4(uint32_t* f, uint32_t addr) {
    asm volatile("ldmatrix.sync.aligned.m8n8.x4.shared.b16 {%0,%1,%2,%3}, [%4];"
                 : "=r"(f[0]), "=r"(f[1]), "=r"(f[2]), "=r"(f[3]) : "r"(addr));
}
__device__ __forceinline__ void mma_16816(float* c, const uint32_t* a, const uint32_t* b) {
    asm volatile("mma.sync.aligned.m16n8k16.row.col.f32.f16.f16.f32 "
                 "{%0,%1,%2,%3}, {%4,%5,%6,%7}, {%8,%9}, {%0,%1,%2,%3};"
                 : "+f"(c[0]), "+f"(c[1]), "+f"(c[2]), "+f"(c[3])
                 : "r"(a[0]), "r"(a[1]), "r"(a[2]), "r"(a[3]), "r"(b[0]), "r"(b[1]));
}
__device__ __forceinline__ void red_add_f32(float* p, float v) {
    asm volatile("red.global.add.f32 [%0], %1;" :: "l"(p), "f"(v) : "memory");
}
__device__ __forceinline__ int ld_acquire(const int* p) {
    int v;
    asm volatile("ld.acquire.gpu.global.b32 %0, [%1];" : "=r"(v) : "l"(p) : "memory");
    return v;
}

__device__ __forceinline__ float gelu_exact(float v) {
    return 0.5f * v * (1.0f + erff(v * 0.70710678118654752f));
}

// ---------------- 0) tiny counter reset ----------------
__global__ void zero_cnt_kernel() {
    int i = threadIdx.x;
    if (i < NTILE * E) ((int*)g_tilecnt)[i] = 0;
    if (i < MAXT) g_done[i] = 0;
    if (i == 0) {
        g_job = 0; g_c1done = 0; g_c2done = 0; g_scatdone = 0;
        g_routdone = 0; g_offsdone = 0;
    }
}

// ---------------- router job (16 tokens; out zeroing + x->fp16 + counts) ---
__device__ __forceinline__ void router_job(int jc,
                                           const float* __restrict__ x,
                                           const float* __restrict__ gw,
                                           const float* __restrict__ gb,
                                           float* __restrict__ out,
                                           float* __restrict__ probs) {
    const int tid = threadIdx.x;
    // zero out slice: tokens [jc*16, jc*16+16) -> 2048 float4
    {
        float4* po = (float4*)(out + (size_t)jc * 16 * D);
#pragma unroll
        for (int k = 0; k < 8; k++)
            po[k * 256 + tid] = make_float4(0.f, 0.f, 0.f, 0.f);
    }
    const int lane = tid & 31, wy = tid >> 5;
#pragma unroll
    for (int pass = 0; pass < 2; pass++) {
        int t = jc * 16 + pass * 8 + wy;
        float acc[E];
#pragma unroll
        for (int e = 0; e < E; e++) acc[e] = 0.0f;
        const float* xr = x + (size_t)t * D;
        __half* xo = g_xh + (size_t)t * D;
        for (int d = lane; d < D; d += 32) {
            float xv = xr[d];
            xo[d] = __float2half_rn(xv);
            const float* g = gw + d * E;
#pragma unroll
            for (int e = 0; e < E; e++) acc[e] += xv * g[e];
        }
#pragma unroll
        for (int e = 0; e < E; e++)
#pragma unroll
            for (int off = 16; off > 0; off >>= 1)
                acc[e] += __shfl_xor_sync(0xffffffffu, acc[e], off);
        if (lane == 0) {
            float p[E]; float mx = -1e30f;
#pragma unroll
            for (int e = 0; e < E; e++) { p[e] = acc[e] + gb[e]; mx = fmaxf(mx, p[e]); }
            float s = 0.0f;
#pragma unroll
            for (int e = 0; e < E; e++) { p[e] = expf(p[e] - mx); s += p[e]; }
            float inv = 1.0f / s;
#pragma unroll
            for (int e = 0; e < E; e++) { p[e] *= inv; probs[(size_t)t * E + e] = p[e]; }
            int i0 = 0; float v0 = p[0];
#pragma unroll
            for (int e = 1; e < E; e++) if (p[e] > v0) { v0 = p[e]; i0 = e; }
            int i1 = -1; float v1 = -1.0f;
#pragma unroll
            for (int e = 0; e < E; e++) if (e != i0 && p[e] > v1) { v1 = p[e]; i1 = e; }
            float ws = 1.0f / (v0 + v1);
            g_topi[2 * t] = i0; g_topi[2 * t + 1] = i1;
            g_topw[2 * t] = v0 * ws; g_topw[2 * t + 1] = v1 * ws;
            int tile = t >> 7;
            atomicAdd(&g_tilecnt[tile][i0], 1);
            atomicAdd(&g_tilecnt[tile][i1], 1);
        }
    }
}

// ---------------- offsets job (single job, 256 threads) ----------------
__device__ __forceinline__ void offsets_job(char* smem) {
    int* sc   = (int*)(smem + 1024);       // NTILE*E ints = 2KB
    int* tot  = (int*)(smem + 1024 + 2048);
    int* offs = (int*)(smem + 1024 + 2048 + 64);
    const int tid = threadIdx.x;
    sc[tid]       = ((const int*)g_tilecnt)[tid];
    sc[tid + 256] = ((const int*)g_tilecnt)[tid + 256];
    __syncthreads();
    if (tid < E) {
        int run = 0;
        for (int b = 0; b < NTILE; b++) {
            int c = sc[b * E + tid];
            sc[b * E + tid] = run;
            run += c;
        }
        tot[tid] = run;
    }
    __syncthreads();
    if (tid == 0) {
        int s = 0;
        for (int e = 0; e < E; e++) { offs[e] = s; g_offs[e] = s; g_count[e] = tot[e]; s += tot[e]; }
        g_offs[E] = s;
        int nt = 0;
        for (int e = 0; e < E; e++)
            for (int mt = 0; mt * 128 < tot[e]; mt++)
                g_tlist[nt++] = (e << 16) | mt;
        g_ntile = nt;
    }
    __syncthreads();
    {
        int i0 = tid, i1 = tid + 256;
        ((int*)g_tileoff)[i0] = sc[i0] + offs[i0 & 7];
        ((int*)g_tileoff)[i1] = sc[i1] + offs[i1 & 7];
    }
}

// ---------------- GEMM tile worker ----------------
// 128x128 tile, BK=32, 4-stage cp.async pipeline, 2 CTAs/SM.
constexpr int MAT_B   = 128 * 80;             // 10240 B
constexpr int STAGE_B = 2 * MAT_B;            // 20480 B
constexpr int SMEM_GEMM = 1024 + 4 * STAGE_B; // 82944 B

template <int KTOT, int NFULL, bool GATHER, bool GELUQ>
__device__ __forceinline__ void gemm_tile(int e, int m0, int n0,
                                          const float* __restrict__ bias,
                                          float* __restrict__ out,
                                          char* smem, uint32_t sb) {
    constexpr int NC = KTOT / 32;
    const int cnt = g_count[e];
    const int base = g_offs[e];
    int* s_tok = (int*)smem;
    const uint32_t TILE = sb + 1024;

    const int tid = threadIdx.x;
    const int lane = tid & 31;
    const int wid = tid >> 5;
    const int wm = (wid >> 2) * 64;
    const int wn = (wid & 3) * 32;

    const __half* Ap = GATHER ? g_xh : g_hh;
    const __half* Bp = GELUQ ? g_w1h : g_w2h;

    if (tid < 128) {
        int r = base + m0 + tid; if (r > AMAX - 1) r = AMAX - 1;
        s_tok[tid] = GATHER ? g_tok[r] : r;
    }
    __syncthreads();

    const __half* srcp[4];
    uint32_t dstoff[4];
#pragma unroll
    for (int i = 0; i < 4; i++) {
        int g = i * 256 + tid;
        int mat = g >> 9, idx = g & 511, row = idx >> 2, seg = idx & 3;
        const __half* sp;
        if (mat == 0) sp = Ap + (size_t)s_tok[row] * KTOT + seg * 8;
        else          sp = Bp + ((size_t)e * NFULL + n0 + row) * KTOT + seg * 8;
        srcp[i] = sp;
        dstoff[i] = (uint32_t)(mat * MAT_B + row * 80 + seg * 16);
    }

    auto load_stage = [&](int c) {
        uint32_t stg = TILE + (c & 3) * STAGE_B;
        int k0 = c * 32;
#pragma unroll
        for (int i = 0; i < 4; i++) cp_async16(stg + dstoff[i], srcp[i] + k0);
    };

    float C[4][4][4];
#pragma unroll
    for (int t = 0; t < 4; t++)
#pragma unroll
        for (int n = 0; n < 4; n++)
#pragma unroll
            for (int j = 0; j < 4; j++) C[t][n][j] = 0.0f;

    load_stage(0); CP_COMMIT();
    load_stage(1); CP_COMMIT();
    load_stage(2); CP_COMMIT();

    const uint32_t a_row_off = (uint32_t)((wm + (lane & 15)) * 80 + ((lane >> 4) << 4));
    const int bq = lane >> 3, br = lane & 7;
    const uint32_t b_row_off = (uint32_t)(MAT_B + (wn + ((bq >> 1) << 3) + br) * 80 + ((bq & 1) << 4));

    for (int c = 0; c < NC; c++) {
        CP_WAIT(2);
        __syncthreads();
        if (c + 3 < NC) load_stage(c + 3);
        CP_COMMIT();

        const uint32_t stg = TILE + (c & 3) * STAGE_B;
#pragma unroll
        for (int s = 0; s < 2; s++) {
            uint32_t af[4][4];
#pragma unroll
            for (int t = 0; t < 4; t++) {
                uint32_t ra = stg + a_row_off + t * (16 * 80) + s * 32;
                ldmatrix_x4(af[t], ra);
            }
            uint32_t bf[4][2];
#pragma unroll
            for (int nb = 0; nb < 2; nb++) {
                uint32_t rb = stg + b_row_off + nb * (16 * 80) + s * 32;
                uint32_t f[4];
                ldmatrix_x4(f, rb);
                bf[nb * 2][0] = f[0]; bf[nb * 2][1] = f[1];
                bf[nb * 2 + 1][0] = f[2]; bf[nb * 2 + 1][1] = f[3];
            }
#pragma unroll
            for (int t = 0; t < 4; t++)
#pragma unroll
                for (int n = 0; n < 4; n++)
                    mma_16816(C[t][n], af[t], bf[n]);
        }
    }

    const float* bb = bias + (size_t)e * NFULL;
#pragma unroll
    for (int t = 0; t < 4; t++) {
#pragma unroll
        for (int n = 0; n < 4; n++) {
            int row = m0 + wm + t * 16 + (lane >> 2);
            int col = n0 + wn + n * 8 + ((lane & 3) << 1);
            float b0v = bb[col], b1v = bb[col + 1];
#pragma unroll
            for (int half = 0; half < 2; half++) {
                int r = row + half * 8;
                if (r < cnt) {
                    float v0 = C[t][n][2 * half + 0] + b0v;
                    float v1 = C[t][n][2 * half + 1] + b1v;
                    if (GELUQ) {
                        size_t o = (size_t)(base + r) * NFULL + col;
                        *(__half2*)(g_hh + o) = __halves2half2(
                            __float2half_rn(gelu_exact(v0)),
                            __float2half_rn(gelu_exact(v1)));
                    } else {
                        int slot = base + r;
                        int tok = g_tok[slot];
                        float w = g_wt[slot];
                        float* op = out + (size_t)tok * NFULL + col;
                        red_add_f32(op,     w * v0);
                        red_add_f32(op + 1, w * v1);
                    }
                }
            }
        }
    }
}

// ---------------- conv / scatter jobs ----------------
__device__ __forceinline__ void conv1_job(int jc, const float* __restrict__ w1, char* smem) {
    float* ts = (float*)(smem + 1024);      // 64 x 33 floats
    const int tid = threadIdx.x;
    const int tx = tid & 31, ty = tid >> 5;
    const int e = jc >> 5;
    const int rem = jc & 31;
    const int d0 = (rem & 7) * 64;
    const int hbase = (rem >> 3) * 256;
    for (int i8 = 0; i8 < 8; i8++) {
        const int h0 = hbase + i8 * 32;
        __syncthreads();
#pragma unroll
        for (int i = 0; i < 8; i++) {
            int r = ty + 8 * i;
            ts[r * 33 + tx] = w1[((size_t)e * D + d0 + r) * HH + h0 + tx];
        }
        __syncthreads();
#pragma unroll
        for (int i = 0; i < 4; i++) {
            int hh = ty + 8 * i;
            __half2 v = __halves2half2(__float2half_rn(ts[(2 * tx) * 33 + hh]),
                                       __float2half_rn(ts[(2 * tx + 1) * 33 + hh]));
            *(__half2*)&g_w1h[((size_t)e * HH + h0 + hh) * D + d0 + 2 * tx] = v;
        }
    }
}
__device__ __forceinline__ void conv2_job(int jc, const float* __restrict__ w2, char* smem) {
    float* ts = (float*)(smem + 1024);
    const int tid = threadIdx.x;
    const int tx = tid & 31, ty = tid >> 5;
    const int e = jc >> 5;
    const int rem = jc & 31;
    const int h0 = (rem & 15) * 64;
    const int dbase = (rem >> 4) * 256;
    for (int i8 = 0; i8 < 8; i8++) {
        const int d0 = dbase + i8 * 32;
        __syncthreads();
#pragma unroll
        for (int i = 0; i < 8; i++) {
            int r = ty + 8 * i;
            ts[r * 33 + tx] = w2[((size_t)e * HH + h0 + r) * D + d0 + tx];
        }
        __syncthreads();
#pragma unroll
        for (int i = 0; i < 4; i++) {
            int dd = ty + 8 * i;
            __half2 v = __halves2half2(__float2half_rn(ts[(2 * tx) * 33 + dd]),
                                       __float2half_rn(ts[(2 * tx + 1) * 33 + dd]));
            *(__half2*)&g_w2h[((size_t)e * D + d0 + dd) * HH + h0 + 2 * tx] = v;
        }
    }
}
__device__ __forceinline__ void scatter_job(int jc, char* smem) {
    int* wc = (int*)(smem + 512);
    const int tid = threadIdx.x;
    if (tid < 128) {
        int t = jc * 128 + tid;
        int lane = tid & 31, w = tid >> 5;
        int e0 = g_topi[2 * t], e1 = g_topi[2 * t + 1];
        unsigned mask[E];
#pragma unroll
        for (int e = 0; e < E; e++) {
            mask[e] = __ballot_sync(0xffffffffu, e0 == e || e1 == e);
            if (lane == 0) wc[w * E + e] = __popc(mask[e]);
        }
        __syncthreads();
#pragma unroll
        for (int e = 0; e < E; e++) {
            if (e == e0 || e == e1) {
                int pre = 0;
#pragma unroll
                for (int ww = 0; ww < 4; ww++) if (ww < w) pre += wc[ww * E + e];
                int pos = g_tileoff[jc][e] + pre + __popc(mask[e] & ((1u << lane) - 1));
                int which = (e == e0) ? 0 : 1;
                g_tok[pos] = t;
                g_wt[pos] = g_topw[2 * t + which];
            }
        }
    } else {
        __syncthreads();
    }
}

// ---------------- persistent mega-kernel ----------------
__global__ __launch_bounds__(256, 2) void moe_mega_kernel(const float* __restrict__ x,
                                                          const float* __restrict__ gw,
                                                          const float* __restrict__ gb,
                                                          const float* __restrict__ w1,
                                                          const float* __restrict__ w2,
                                                          const float* __restrict__ b1,
                                                          const float* __restrict__ b2,
                                                          float* __restrict__ out,
                                                          float* __restrict__ probs) {
    extern __shared__ char smem[];
    const uint32_t sb = smem_u32(smem);
    __shared__ int s_job;
    const int tid = threadIdx.x;
    const int bid = blockIdx.x;

    // -------- phase A: statically assigned aux jobs (no dispatch atomics) --
    for (int j = bid; j < NAUX; j += GRID) {
        if (j < JR) {
            router_job(j, x, gw, gb, out, probs);
            __syncthreads();
            if (tid == 0) { __threadfence(); atomicAdd(&g_routdone, 1); }
        } else if (j < JR + NC1) {
            conv1_job(j - JR, w1, smem);
            __syncthreads();
            if (tid == 0) { __threadfence(); atomicAdd(&g_c1done, 1); }
        } else {
            conv2_job(j - JR - NC1, w2, smem);
            __syncthreads();
            if (tid == 0) { __threadfence(); atomicAdd(&g_c2done, 1); }
        }
        __syncthreads();
    }

    // -------- offsets (CTA 0) and scatter (CTAs 1..64), static ------------
    if (bid == 0) {
        if (tid == 0) { while (ld_acquire(&g_routdone) < JR) __nanosleep(64); }
        __syncthreads();
        offsets_job(smem);
        __syncthreads();
        if (tid == 0) { __threadfence(); atomicAdd(&g_offsdone, 1); }
    } else if (bid <= NS) {
        if (tid == 0) { while (ld_acquire(&g_offsdone) < 1) __nanosleep(64); }
        __syncthreads();
        scatter_job(bid - 1, smem);
        __syncthreads();
        if (tid == 0) { __threadfence(); atomicAdd(&g_scatdone, 1); }
    }

    // -------- phase B: dynamic GEMM jobs ----------------------------------
    for (;;) {
        if (tid == 0) s_job = atomicAdd(&g_job, 1);
        __syncthreads();
        const int j = s_job;
        if (j >= NJOBS) break;

        if (j < NJ1) {
            // GEMM1 tile
            const int mt = j >> 3, n0 = (j & 7) * 128;
            if (tid == 0) {
                while (ld_acquire(&g_scatdone) < NS || ld_acquire(&g_c1done) < NC1)
                    __nanosleep(64);
            }
            __syncthreads();
            if (mt < g_ntile) {
                const int ent = g_tlist[mt];
                gemm_tile<512, 1024, true, true>(ent >> 16, (ent & 0xFFFF) * 128, n0,
                                                 b1, out, smem, sb);
                __syncthreads();
                if (tid == 0) { __threadfence(); atomicAdd(&g_done[mt], 1); }
            }
        } else {
            // GEMM2 tile
            const int jj = j - NJ1;
            const int mt = jj >> 2, n0 = (jj & 3) * 128;
            if (tid == 0) {
                while (ld_acquire(&g_scatdone) < NS || ld_acquire(&g_c2done) < NC2)
                    __nanosleep(64);
            }
            __syncthreads();
            if (mt < g_ntile) {
                const int ent = g_tlist[mt];
                if (tid == 0) {
                    while (ld_acquire(&g_done[mt]) < 8) __nanosleep(64);
                }
                __syncthreads();
                gemm_tile<1024, 512, false, false>(ent >> 16, (ent & 0xFFFF) * 128, n0,
                                                   b2, out, smem, sb);
                __syncthreads();
            }
        }
    }
}

// ---------------- host ----------------
extern "C" void kernel_launch(void* const* d_in, const int* in_sizes, int n_in,
                              void* d_out, int out_size) {
    const float* x      = (const float*)d_in[0];
    const float* gate_w = (const float*)d_in[1];
    const float* gate_b = (const float*)d_in[2];
    const float* w1     = (const float*)d_in[3];
    const float* b1     = (const float*)d_in[4];
    const float* w2     = (const float*)d_in[5];
    const float* b2     = (const float*)d_in[6];

    float* out   = (float*)d_out;
    float* probs = out + (size_t)NTOK * D;

    cudaFuncSetAttribute(moe_mega_kernel,
                         cudaFuncAttributeMaxDynamicSharedMemorySize, SMEM_GEMM);

    zero_cnt_kernel<<<1, 1024>>>();
    moe_mega_kernel<<<GRID, 256, SMEM_GEMM>>>(x, gate_w, gate_b, w1, w2, b1, b2,
                                              out, probs);
}

// round 16
// speedup vs baseline: 1.2042x; 1.2042x over previous
#include <cuda_runtime.h>
#include <cuda_fp16.h>
#include <math.h>
#include <stdint.h>

// ---------------- problem constants ----------------
constexpr int E    = 8;
constexpr int D    = 512;
constexpr int HH   = 1024;
constexpr int NTOK = 8192;
constexpr int AMAX = NTOK * 2;     // exactly 2 assignments per token
constexpr int NTILE = 64;          // routing tiles of 128 tokens
constexpr int MAXT  = 136;         // max total m-tiles: 128 + E

// job layout inside the persistent kernel (same as R14)
constexpr int JR   = 512;                // router jobs (16 tokens each)
constexpr int NC1  = 256;                // conv_w1 jobs
constexpr int NC2  = 256;                // conv_w2 jobs
constexpr int NS   = 64;                 // scatter jobs (128 tokens each)
constexpr int JB_C1   = JR;              // 512
constexpr int JB_C2   = JB_C1 + NC1;     // 768
constexpr int JB_OFF  = JB_C2 + NC2;     // 1024
constexpr int JB_SCAT = JB_OFF + 1;      // 1025
constexpr int JB_G1   = JB_SCAT + NS;    // 1089
constexpr int JB_G2   = JB_G1 + MAXT * 8;   // 2177
constexpr int NJOBS   = JB_G2 + MAXT * 4;   // 2721

// ---------------- device scratch (static; no allocation) ----------------
__device__ __half g_xh[(size_t)NTOK * D];      // x in fp16
__device__ __half g_w1h[(size_t)E * HH * D];   // [E][H][D]  (w1 transposed, fp16)
__device__ __half g_w2h[(size_t)E * D * HH];   // [E][D][H]  (w2 transposed, fp16)
__device__ __half g_hh[(size_t)AMAX * HH];     // gelu(h) fp16

__device__ int   g_tok[AMAX];
__device__ float g_wt[AMAX];
__device__ int   g_topi[NTOK * 2];
__device__ float g_topw[NTOK * 2];
__device__ int   g_count[E];
__device__ int   g_offs[E + 1];
__device__ int   g_tilecnt[NTILE][E];
__device__ int   g_tileoff[NTILE][E];
__device__ int   g_tlist[MAXT];
__device__ int   g_ntile;
__device__ int   g_done[MAXT];     // per-m-tile GEMM1 completion count
__device__ int   g_job;            // persistent-kernel job counter
__device__ int   g_c1done, g_c2done, g_scatdone, g_routdone, g_offsdone;

// ---------------- PTX helpers (baseline sm_80/90; no arch-'a' features) ----
__device__ __forceinline__ uint32_t smem_u32(const void* p) {
    uint32_t a;
    asm("{ .reg .u64 t; cvta.to.shared.u64 t, %1; cvt.u32.u64 %0, t; }" : "=r"(a) : "l"(p));
    return a;
}
__device__ __forceinline__ void cp_async16(uint32_t dst, const void* src) {
    asm volatile("cp.async.cg.shared.global [%0], [%1], 16;" :: "r"(dst), "l"(src));
}
#define CP_COMMIT() asm volatile("cp.async.commit_group;" ::: "memory")
#define CP_WAIT(n)  asm volatile("cp.async.wait_group %0;" :: "n"(n) : "memory")

__device__ __forceinline__ void ldmatrix_x4(uint32_t* f, uint32_t addr) {
    asm volatile("ldmatrix.sync.aligned.m8n8.x4.shared.b16 {%0,%1,%2,%3}, [%4];"
                 : "=r"(f[0]), "=r"(f[1]), "=r"(f[2]), "=r"(f[3]) : "r"(addr));
}
__device__ __forceinline__ void mma_16816(float* c, const uint32_t* a, const uint32_t* b) {
    asm volatile("mma.sync.aligned.m16n8k16.row.col.f32.f16.f16.f32 "
                 "{%0,%1,%2,%3}, {%4,%5,%6,%7}, {%8,%9}, {%0,%1,%2,%3};"
                 : "+f"(c[0]), "+f"(c[1]), "+f"(c[2]), "+f"(c[3])
                 : "r"(a[0]), "r"(a[1]), "r"(a[2]), "r"(a[3]), "r"(b[0]), "r"(b[1]));
}
__device__ __forceinline__ void red_add_f32(float* p, float v) {
    asm volatile("red.global.add.f32 [%0], %1;" :: "l"(p), "f"(v) : "memory");
}
__device__ __forceinline__ int ld_acquire(const int* p) {
    int v;
    asm volatile("ld.acquire.gpu.global.b32 %0, [%1];" : "=r"(v) : "l"(p) : "memory");
    return v;
}

__device__ __forceinline__ float gelu_exact(float v) {
    return 0.5f * v * (1.0f + erff(v * 0.70710678118654752f));
}

// ---------------- 0) tiny counter reset ----------------
__global__ void zero_cnt_kernel() {
    int i = threadIdx.x;
    if (i < NTILE * E) ((int*)g_tilecnt)[i] = 0;
    if (i < MAXT) g_done[i] = 0;
    if (i == 0) {
        g_job = 0; g_c1done = 0; g_c2done = 0; g_scatdone = 0;
        g_routdone = 0; g_offsdone = 0;
    }
}

// ---------------- router job (16 tokens; smem-transposed gw) ---------------
// gwT[e][d] staged in smem: inner-loop gw reads become conflict-free LDS
// (32 consecutive words per instruction) instead of 32-way-split LDGs.
// Per-lane accumulation order identical to previous rounds -> bitwise same.
__device__ __forceinline__ void router_job(int jc,
                                           const float* __restrict__ x,
                                           const float* __restrict__ gw,
                                           const float* __restrict__ gb,
                                           float* __restrict__ out,
                                           float* __restrict__ probs,
                                           char* smem) {
    const int tid = threadIdx.x;
    float* gwT = (float*)(smem + 4096);    // 8 x 512 floats = 16 KB
    // stage gw transposed: linear coalesced read, scattered smem write
    for (int i = tid; i < D * E; i += 256) {
        gwT[(i & 7) * D + (i >> 3)] = gw[i];    // i = d*E + e
    }
    // zero out slice: tokens [jc*16, jc*16+16) -> 2048 float4
    {
        float4* po = (float4*)(out + (size_t)jc * 16 * D);
#pragma unroll
        for (int k = 0; k < 8; k++)
            po[k * 256 + tid] = make_float4(0.f, 0.f, 0.f, 0.f);
    }
    __syncthreads();
    const int lane = tid & 31, wy = tid >> 5;
#pragma unroll
    for (int pass = 0; pass < 2; pass++) {
        int t = jc * 16 + pass * 8 + wy;
        float acc[E];
#pragma unroll
        for (int e = 0; e < E; e++) acc[e] = 0.0f;
        const float* xr = x + (size_t)t * D;
        __half* xo = g_xh + (size_t)t * D;
        for (int d = lane; d < D; d += 32) {
            float xv = xr[d];
            xo[d] = __float2half_rn(xv);
#pragma unroll
            for (int e = 0; e < E; e++) acc[e] += xv * gwT[e * D + d];
        }
#pragma unroll
        for (int e = 0; e < E; e++)
#pragma unroll
            for (int off = 16; off > 0; off >>= 1)
                acc[e] += __shfl_xor_sync(0xffffffffu, acc[e], off);
        if (lane == 0) {
            float p[E]; float mx = -1e30f;
#pragma unroll
            for (int e = 0; e < E; e++) { p[e] = acc[e] + gb[e]; mx = fmaxf(mx, p[e]); }
            float s = 0.0f;
#pragma unroll
            for (int e = 0; e < E; e++) { p[e] = expf(p[e] - mx); s += p[e]; }
            float inv = 1.0f / s;
#pragma unroll
            for (int e = 0; e < E; e++) { p[e] *= inv; probs[(size_t)t * E + e] = p[e]; }
            int i0 = 0; float v0 = p[0];
#pragma unroll
            for (int e = 1; e < E; e++) if (p[e] > v0) { v0 = p[e]; i0 = e; }
            int i1 = -1; float v1 = -1.0f;
#pragma unroll
            for (int e = 0; e < E; e++) if (e != i0 && p[e] > v1) { v1 = p[e]; i1 = e; }
            float ws = 1.0f / (v0 + v1);
            g_topi[2 * t] = i0; g_topi[2 * t + 1] = i1;
            g_topw[2 * t] = v0 * ws; g_topw[2 * t + 1] = v1 * ws;
            int tile = t >> 7;
            atomicAdd(&g_tilecnt[tile][i0], 1);
            atomicAdd(&g_tilecnt[tile][i1], 1);
        }
    }
}

// ---------------- offsets job (single job, 256 threads) ----------------
__device__ __forceinline__ void offsets_job(char* smem) {
    int* sc   = (int*)(smem + 1024);       // NTILE*E ints = 2KB
    int* tot  = (int*)(smem + 1024 + 2048);
    int* offs = (int*)(smem + 1024 + 2048 + 64);
    const int tid = threadIdx.x;
    sc[tid]       = ((const int*)g_tilecnt)[tid];
    sc[tid + 256] = ((const int*)g_tilecnt)[tid + 256];
    __syncthreads();
    if (tid < E) {
        int run = 0;
        for (int b = 0; b < NTILE; b++) {
            int c = sc[b * E + tid];
            sc[b * E + tid] = run;
            run += c;
        }
        tot[tid] = run;
    }
    __syncthreads();
    if (tid == 0) {
        int s = 0;
        for (int e = 0; e < E; e++) { offs[e] = s; g_offs[e] = s; g_count[e] = tot[e]; s += tot[e]; }
        g_offs[E] = s;
        int nt = 0;
        for (int e = 0; e < E; e++)
            for (int mt = 0; mt * 128 < tot[e]; mt++)
                g_tlist[nt++] = (e << 16) | mt;
        g_ntile = nt;
    }
    __syncthreads();
    {
        int i0 = tid, i1 = tid + 256;
        ((int*)g_tileoff)[i0] = sc[i0] + offs[i0 & 7];
        ((int*)g_tileoff)[i1] = sc[i1] + offs[i1 & 7];
    }
}

// ---------------- GEMM tile worker ----------------
// 128x128 tile, BK=32, 4-stage cp.async pipeline, 2 CTAs/SM.
constexpr int MAT_B   = 128 * 80;             // 10240 B
constexpr int STAGE_B = 2 * MAT_B;            // 20480 B
constexpr int SMEM_GEMM = 1024 + 4 * STAGE_B; // 82944 B

template <int KTOT, int NFULL, bool GATHER, bool GELUQ>
__device__ __forceinline__ void gemm_tile(int e, int m0, int n0,
                                          const float* __restrict__ bias,
                                          float* __restrict__ out,
                                          char* smem, uint32_t sb) {
    constexpr int NC = KTOT / 32;
    const int cnt = g_count[e];
    const int base = g_offs[e];
    int* s_tok = (int*)smem;
    const uint32_t TILE = sb + 1024;

    const int tid = threadIdx.x;
    const int lane = tid & 31;
    const int wid = tid >> 5;
    const int wm = (wid >> 2) * 64;
    const int wn = (wid & 3) * 32;

    const __half* Ap = GATHER ? g_xh : g_hh;
    const __half* Bp = GELUQ ? g_w1h : g_w2h;

    if (tid < 128) {
        int r = base + m0 + tid; if (r > AMAX - 1) r = AMAX - 1;
        s_tok[tid] = GATHER ? g_tok[r] : r;
    }
    __syncthreads();

    const __half* srcp[4];
    uint32_t dstoff[4];
#pragma unroll
    for (int i = 0; i < 4; i++) {
        int g = i * 256 + tid;
        int mat = g >> 9, idx = g & 511, row = idx >> 2, seg = idx & 3;
        const __half* sp;
        if (mat == 0) sp = Ap + (size_t)s_tok[row] * KTOT + seg * 8;
        else          sp = Bp + ((size_t)e * NFULL + n0 + row) * KTOT + seg * 8;
        srcp[i] = sp;
        dstoff[i] = (uint32_t)(mat * MAT_B + row * 80 + seg * 16);
    }

    auto load_stage = [&](int c) {
        uint32_t stg = TILE + (c & 3) * STAGE_B;
        int k0 = c * 32;
#pragma unroll
        for (int i = 0; i < 4; i++) cp_async16(stg + dstoff[i], srcp[i] + k0);
    };

    float C[4][4][4];
#pragma unroll
    for (int t = 0; t < 4; t++)
#pragma unroll
        for (int n = 0; n < 4; n++)
#pragma unroll
            for (int j = 0; j < 4; j++) C[t][n][j] = 0.0f;

    load_stage(0); CP_COMMIT();
    load_stage(1); CP_COMMIT();
    load_stage(2); CP_COMMIT();

    const uint32_t a_row_off = (uint32_t)((wm + (lane & 15)) * 80 + ((lane >> 4) << 4));
    const int bq = lane >> 3, br = lane & 7;
    const uint32_t b_row_off = (uint32_t)(MAT_B + (wn + ((bq >> 1) << 3) + br) * 80 + ((bq & 1) << 4));

    for (int c = 0; c < NC; c++) {
        CP_WAIT(2);
        __syncthreads();
        if (c + 3 < NC) load_stage(c + 3);
        CP_COMMIT();

        const uint32_t stg = TILE + (c & 3) * STAGE_B;
#pragma unroll
        for (int s = 0; s < 2; s++) {
            uint32_t af[4][4];
#pragma unroll
            for (int t = 0; t < 4; t++) {
                uint32_t ra = stg + a_row_off + t * (16 * 80) + s * 32;
                ldmatrix_x4(af[t], ra);
            }
            uint32_t bf[4][2];
#pragma unroll
            for (int nb = 0; nb < 2; nb++) {
                uint32_t rb = stg + b_row_off + nb * (16 * 80) + s * 32;
                uint32_t f[4];
                ldmatrix_x4(f, rb);
                bf[nb * 2][0] = f[0]; bf[nb * 2][1] = f[1];
                bf[nb * 2 + 1][0] = f[2]; bf[nb * 2 + 1][1] = f[3];
            }
#pragma unroll
            for (int t = 0; t < 4; t++)
#pragma unroll
                for (int n = 0; n < 4; n++)
                    mma_16816(C[t][n], af[t], bf[n]);
        }
    }

    const float* bb = bias + (size_t)e * NFULL;
#pragma unroll
    for (int t = 0; t < 4; t++) {
#pragma unroll
        for (int n = 0; n < 4; n++) {
            int row = m0 + wm + t * 16 + (lane >> 2);
            int col = n0 + wn + n * 8 + ((lane & 3) << 1);
            float b0v = bb[col], b1v = bb[col + 1];
#pragma unroll
            for (int half = 0; half < 2; half++) {
                int r = row + half * 8;
                if (r < cnt) {
                    float v0 = C[t][n][2 * half + 0] + b0v;
                    float v1 = C[t][n][2 * half + 1] + b1v;
                    if (GELUQ) {
                        size_t o = (size_t)(base + r) * NFULL + col;
                        *(__half2*)(g_hh + o) = __halves2half2(
                            __float2half_rn(gelu_exact(v0)),
                            __float2half_rn(gelu_exact(v1)));
                    } else {
                        int slot = base + r;
                        int tok = g_tok[slot];
                        float w = g_wt[slot];
                        float* op = out + (size_t)tok * NFULL + col;
                        red_add_f32(op,     w * v0);
                        red_add_f32(op + 1, w * v1);
                    }
                }
            }
        }
    }
}

// ---------------- conv / scatter jobs ----------------
__device__ __forceinline__ void conv1_job(int jc, const float* __restrict__ w1, char* smem) {
    float* ts = (float*)(smem + 1024);      // 64 x 33 floats
    const int tid = threadIdx.x;
    const int tx = tid & 31, ty = tid >> 5;
    const int e = jc >> 5;
    const int rem = jc & 31;
    const int d0 = (rem & 7) * 64;
    const int hbase = (rem >> 3) * 256;
    for (int i8 = 0; i8 < 8; i8++) {
        const int h0 = hbase + i8 * 32;
        __syncthreads();
#pragma unroll
        for (int i = 0; i < 8; i++) {
            int r = ty + 8 * i;
            ts[r * 33 + tx] = w1[((size_t)e * D + d0 + r) * HH + h0 + tx];
        }
        __syncthreads();
#pragma unroll
        for (int i = 0; i < 4; i++) {
            int hh = ty + 8 * i;
            __half2 v = __halves2half2(__float2half_rn(ts[(2 * tx) * 33 + hh]),
                                       __float2half_rn(ts[(2 * tx + 1) * 33 + hh]));
            *(__half2*)&g_w1h[((size_t)e * HH + h0 + hh) * D + d0 + 2 * tx] = v;
        }
    }
}
__device__ __forceinline__ void conv2_job(int jc, const float* __restrict__ w2, char* smem) {
    float* ts = (float*)(smem + 1024);
    const int tid = threadIdx.x;
    const int tx = tid & 31, ty = tid >> 5;
    const int e = jc >> 5;
    const int rem = jc & 31;
    const int h0 = (rem & 15) * 64;
    const int dbase = (rem >> 4) * 256;
    for (int i8 = 0; i8 < 8; i8++) {
        const int d0 = dbase + i8 * 32;
        __syncthreads();
#pragma unroll
        for (int i = 0; i < 8; i++) {
            int r = ty + 8 * i;
            ts[r * 33 + tx] = w2[((size_t)e * HH + h0 + r) * D + d0 + tx];
        }
        __syncthreads();
#pragma unroll
        for (int i = 0; i < 4; i++) {
            int dd = ty + 8 * i;
            __half2 v = __halves2half2(__float2half_rn(ts[(2 * tx) * 33 + dd]),
                                       __float2half_rn(ts[(2 * tx + 1) * 33 + dd]));
            *(__half2*)&g_w2h[((size_t)e * D + d0 + dd) * HH + h0 + 2 * tx] = v;
        }
    }
}
__device__ __forceinline__ void scatter_job(int jc, char* smem) {
    int* wc = (int*)(smem + 512);
    const int tid = threadIdx.x;
    if (tid < 128) {
        int t = jc * 128 + tid;
        int lane = tid & 31, w = tid >> 5;
        int e0 = g_topi[2 * t], e1 = g_topi[2 * t + 1];
        unsigned mask[E];
#pragma unroll
        for (int e = 0; e < E; e++) {
            mask[e] = __ballot_sync(0xffffffffu, e0 == e || e1 == e);
            if (lane == 0) wc[w * E + e] = __popc(mask[e]);
        }
        __syncthreads();
#pragma unroll
        for (int e = 0; e < E; e++) {
            if (e == e0 || e == e1) {
                int pre = 0;
#pragma unroll
                for (int ww = 0; ww < 4; ww++) if (ww < w) pre += wc[ww * E + e];
                int pos = g_tileoff[jc][e] + pre + __popc(mask[e] & ((1u << lane) - 1));
                int which = (e == e0) ? 0 : 1;
                g_tok[pos] = t;
                g_wt[pos] = g_topw[2 * t + which];
            }
        }
    } else {
        __syncthreads();
    }
}

// ---------------- persistent mega-kernel ----------------
__global__ __launch_bounds__(256, 2) void moe_mega_kernel(const float* __restrict__ x,
                                                          const float* __restrict__ gw,
                                                          const float* __restrict__ gb,
                                                          const float* __restrict__ w1,
                                                          const float* __restrict__ w2,
                                                          const float* __restrict__ b1,
                                                          const float* __restrict__ b2,
                                                          float* __restrict__ out,
                                                          float* __restrict__ probs) {
    extern __shared__ char smem[];
    const uint32_t sb = smem_u32(smem);
    __shared__ int s_job;
    const int tid = threadIdx.x;

    for (;;) {
        if (tid == 0) s_job = atomicAdd(&g_job, 1);
        __syncthreads();
        const int j = s_job;
        if (j >= NJOBS) break;

        if (j < JB_C1) {
            router_job(j, x, gw, gb, out, probs, smem);
            __syncthreads();
            if (tid == 0) { __threadfence(); atomicAdd(&g_routdone, 1); }
        } else if (j < JB_C2) {
            conv1_job(j - JB_C1, w1, smem);
            __syncthreads();
            if (tid == 0) { __threadfence(); atomicAdd(&g_c1done, 1); }
        } else if (j < JB_OFF) {
            conv2_job(j - JB_C2, w2, smem);
            __syncthreads();
            if (tid == 0) { __threadfence(); atomicAdd(&g_c2done, 1); }
        } else if (j == JB_OFF) {
            if (tid == 0) {
                while (ld_acquire(&g_routdone) < JR) __nanosleep(64);
            }
            __syncthreads();
            offsets_job(smem);
            __syncthreads();
            if (tid == 0) { __threadfence(); atomicAdd(&g_offsdone, 1); }
        } else if (j < JB_G1) {
            if (tid == 0) {
                while (ld_acquire(&g_offsdone) < 1) __nanosleep(64);
            }
            __syncthreads();
            scatter_job(j - JB_SCAT, smem);
            __syncthreads();
            if (tid == 0) { __threadfence(); atomicAdd(&g_scatdone, 1); }
        } else if (j < JB_G2) {
            // GEMM1 tile
            const int jj = j - JB_G1;
            const int mt = jj >> 3, n0 = (jj & 7) * 128;
            if (tid == 0) {
                while (ld_acquire(&g_offsdone) < 1) __nanosleep(64);
            }
            __syncthreads();
            if (mt < g_ntile) {
                const int ent = g_tlist[mt];
                if (tid == 0) {
                    while (ld_acquire(&g_c1done) < NC1 || ld_acquire(&g_scatdone) < NS)
                        __nanosleep(64);
                }
                __syncthreads();
                gemm_tile<512, 1024, true, true>(ent >> 16, (ent & 0xFFFF) * 128, n0,
                                                 b1, out, smem, sb);
                __syncthreads();
                if (tid == 0) { __threadfence(); atomicAdd(&g_done[mt], 1); }
            }
        } else {
            // GEMM2 tile
            const int jj = j - JB_G2;
            const int mt = jj >> 2, n0 = (jj & 3) * 128;
            if (tid == 0) {
                while (ld_acquire(&g_offsdone) < 1) __nanosleep(64);
            }
            __syncthreads();
            if (mt < g_ntile) {
                const int ent = g_tlist[mt];
                if (tid == 0) {
                    while (ld_acquire(&g_c2done) < NC2 || ld_acquire(&g_done[mt]) < 8)
                        __nanosleep(64);
                }
                __syncthreads();
                gemm_tile<1024, 512, false, false>(ent >> 16, (ent & 0xFFFF) * 128, n0,
                                                   b2, out, smem, sb);
                __syncthreads();
            }
        }
    }
}

// ---------------- host ----------------
extern "C" void kernel_launch(void* const* d_in, const int* in_sizes, int n_in,
                              void* d_out, int out_size) {
    const float* x      = (const float*)d_in[0];
    const float* gate_w = (const float*)d_in[1];
    const float* gate_b = (const float*)d_in[2];
    const float* w1     = (const float*)d_in[3];
    const float* b1     = (const float*)d_in[4];
    const float* w2     = (const float*)d_in[5];
    const float* b2     = (const float*)d_in[6];

    float* out   = (float*)d_out;
    float* probs = out + (size_t)NTOK * D;

    cudaFuncSetAttribute(moe_mega_kernel,
                         cudaFuncAttributeMaxDynamicSharedMemorySize, SMEM_GEMM);

    zero_cnt_kernel<<<1, 1024>>>();
    moe_mega_kernel<<<304, 256, SMEM_GEMM>>>(x, gate_w, gate_b, w1, w2, b1, b2,
                                             out, probs);
}